// round 9
// baseline (speedup 1.0000x reference)
#include <cuda_runtime.h>

#define H_IN   200
#define W_IN   320
#define C_IN   64
#define H_OUT  48
#define W_OUT  320

#define SRC_CH_STRIDE (H_IN * W_IN)    // 64000 floats
#define DST_CH_STRIDE (H_OUT * W_OUT)  // 15360 floats

#define QUADS     (W_OUT / 4)          // 80 column-quads per row
#define NTHREADS  256
#define NUNITS    (H_OUT * QUADS)      // 3840 float4 units per (box,channel) tile
#define CPAIR     2                    // channels per block

__global__ void __launch_bounds__(NTHREADS)
roi_crop_kernel(const float* __restrict__ x,
                const int*   __restrict__ bboxes,
                const int*   __restrict__ box_img,
                float*       __restrict__ out)
{
    const int c0 = blockIdx.x * CPAIR;  // first channel of the pair
    const int b  = blockIdx.y;          // box 0..255
    const int t  = threadIdx.x;         // 0..255

    __shared__ int4 s_colq[QUADS];      // 4 source cols per output quad
    __shared__ int  s_row[H_OUT];       // source row per output row

    // bbox decode (uniform per block)
    int x0 = __ldg(&bboxes[b * 4 + 0]);
    int y0 = __ldg(&bboxes[b * 4 + 1]);
    int x1 = __ldg(&bboxes[b * 4 + 2]);
    int y1 = __ldg(&bboxes[b * 4 + 3]);
    x0 = min(max(x0, 0), W_IN - 1);
    y0 = min(max(y0, 0), H_IN - 1);
    x1 = min(max(x1, 0), W_IN - 1);
    y1 = min(max(y1, 0), H_IN - 1);
    x1 = max(x1, x0);
    y1 = max(y1, y0);
    const int h = y1 - y0 + 1;
    const int w = x1 - x0 + 1;

    if (t < QUADS) {                         // 80 threads fill column quads
        const int j0 = t * 4;
        int4 cq;
        cq.x = x0 + ((j0 + 0) * w) / W_OUT;  // const-divisor -> mul/shift
        cq.y = x0 + ((j0 + 1) * w) / W_OUT;
        cq.z = x0 + ((j0 + 2) * w) / W_OUT;
        cq.w = x0 + ((j0 + 3) * w) / W_OUT;
        s_colq[t] = cq;
    }
    if (t >= 128 && t < 128 + H_OUT)         // 48 threads fill row map
        s_row[t - 128] = y0 + ((t - 128) * h) / H_OUT;
    __syncthreads();

    const int img = __ldg(&box_img[b]);
    const float* __restrict__ src0 =
        x + (size_t)img * (C_IN * SRC_CH_STRIDE) + (size_t)c0 * SRC_CH_STRIDE;
    float4* __restrict__ dst0 =
        (float4*)(out + ((size_t)b * C_IN + c0) * DST_CH_STRIDE);

    // Two consecutive channel tiles, written back-to-back in time:
    // 2 x 61440 B = 122,880 B of block-sequential DRAM writes.
    #pragma unroll
    for (int cc = 0; cc < CPAIR; cc++) {
        const float* __restrict__ src = src0 + cc * SRC_CH_STRIDE;
        float4* __restrict__ dst = dst0 + cc * (DST_CH_STRIDE / 4);

        #pragma unroll 5
        for (int u = t; u < NUNITS; u += NTHREADS) {
            const int i = u / QUADS;             // output row
            const int q = u - i * QUADS;         // quad within row
            const int4 cq = s_colq[q];           // LDS.128, conflict-free
            const float* __restrict__ s = src + s_row[i] * W_IN;
            float4 v;
            v.x = __ldg(s + cq.x);
            v.y = __ldg(s + cq.y);
            v.z = __ldg(s + cq.z);
            v.w = __ldg(s + cq.w);
            __stcs(dst + u, v);                  // streaming store, evict-first
        }
    }
}

extern "C" void kernel_launch(void* const* d_in, const int* in_sizes, int n_in,
                              void* d_out, int out_size)
{
    const float* x       = (const float*)d_in[0];
    const int*   bboxes  = (const int*)d_in[1];
    const int*   box_img = (const int*)d_in[2];
    float*       out     = (float*)d_out;

    dim3 grid(C_IN / CPAIR, 256);         // (32 channel-pairs, 256 boxes)
    roi_crop_kernel<<<grid, NTHREADS>>>(x, bboxes, box_img, out);
}